// round 1
// baseline (speedup 1.0000x reference)
#include <cuda_runtime.h>
#include <cuda_bf16.h>
#include <cstddef>

// CAN module: per-sample 2-layer MLP, B=16384, N=50, D=16.
//   x (B,N,D) fp32 ; params (B, 2*(D*D+D)) packed [W0, b0, W1, b1]
//   x = relu(x @ W + b) twice.
//
// Strategy: warp-per-sample.
//   lane l: column e = l & 15, row-parity half = l >> 4 (rows n = 2i + half).
//   W columns live in registers; x tile staged in shared (float4), layers
//   computed in place (row-local dependence), output streamed coalesced.

#define CAN_D 16
#define CAN_N 50
#define CAN_WARPS 8
#define PARAMS_PER 544   // 2*(16*16 + 16)

__global__ __launch_bounds__(32 * CAN_WARPS)
void can_kernel(const float* __restrict__ user,
                const float* __restrict__ item,
                float* __restrict__ out,
                int B)
{
    __shared__ float xs[CAN_WARPS][CAN_N * CAN_D];  // 8 * 800 * 4 = 25.6 KB

    const int warp = threadIdx.x >> 5;
    const int lane = threadIdx.x & 31;
    const int sample = blockIdx.x * CAN_WARPS + warp;
    if (sample >= B) return;

    const float* __restrict__ xin = user + (size_t)sample * (CAN_N * CAN_D);
    const float* __restrict__ prm = item + (size_t)sample * PARAMS_PER;

    // --- stage x into shared, float4-coalesced (200 float4 per warp) ---
    {
        float4* dst4 = reinterpret_cast<float4*>(xs[warp]);
        const float4* src4 = reinterpret_cast<const float4*>(xin);
        #pragma unroll
        for (int i = 0; i < (CAN_N * CAN_D / 4 + 31) / 32; ++i) {
            int idx = lane + 32 * i;
            if (idx < CAN_N * CAN_D / 4) dst4[idx] = src4[idx];
        }
    }

    const int e    = lane & 15;
    const int half = lane >> 4;

    // --- W columns into registers (broadcast 64B segments; read once) ---
    float w0[CAN_D], w1[CAN_D];
    #pragma unroll
    for (int d = 0; d < CAN_D; ++d) w0[d] = prm[d * CAN_D + e];
    const float b0 = prm[CAN_D * CAN_D + e];                       // 256 + e
    #pragma unroll
    for (int d = 0; d < CAN_D; ++d) w1[d] = prm[272 + d * CAN_D + e];
    const float b1 = prm[528 + e];

    __syncwarp();

    // --- layer 1: read all rows into regs, then overwrite shared in place ---
    float acc[CAN_N / 2];
    {
        const float4* s4 = reinterpret_cast<const float4*>(xs[warp]);
        #pragma unroll
        for (int i = 0; i < CAN_N / 2; ++i) {
            const int n = 2 * i + half;
            float a = b0;
            #pragma unroll
            for (int q = 0; q < 4; ++q) {
                float4 v = s4[n * 4 + q];   // LDS.128 broadcast within half-warp
                a = fmaf(v.x, w0[4 * q + 0], a);
                a = fmaf(v.y, w0[4 * q + 1], a);
                a = fmaf(v.z, w0[4 * q + 2], a);
                a = fmaf(v.w, w0[4 * q + 3], a);
            }
            acc[i] = fmaxf(a, 0.0f);
        }
        __syncwarp();
        #pragma unroll
        for (int i = 0; i < CAN_N / 2; ++i) {
            const int n = 2 * i + half;
            xs[warp][n * CAN_D + e] = acc[i];
        }
        __syncwarp();
    }

    // --- layer 2: read shared, write straight to global (coalesced 128B) ---
    {
        const float4* s4 = reinterpret_cast<const float4*>(xs[warp]);
        float* __restrict__ o = out + (size_t)sample * (CAN_N * CAN_D);
        #pragma unroll
        for (int i = 0; i < CAN_N / 2; ++i) {
            const int n = 2 * i + half;
            float a = b1;
            #pragma unroll
            for (int q = 0; q < 4; ++q) {
                float4 v = s4[n * 4 + q];
                a = fmaf(v.x, w1[4 * q + 0], a);
                a = fmaf(v.y, w1[4 * q + 1], a);
                a = fmaf(v.z, w1[4 * q + 2], a);
                a = fmaf(v.w, w1[4 * q + 3], a);
            }
            // lanes 0..31 of iteration i cover flat offsets 32i .. 32i+31
            o[n * CAN_D + e] = fmaxf(a, 0.0f);
        }
    }
}

extern "C" void kernel_launch(void* const* d_in, const int* in_sizes, int n_in,
                              void* d_out, int out_size)
{
    const float* user = (const float*)d_in[0];
    const float* item = (const float*)d_in[1];
    float* out = (float*)d_out;

    const int B = in_sizes[0] / (CAN_N * CAN_D);   // 16384
    const int grid = (B + CAN_WARPS - 1) / CAN_WARPS;

    can_kernel<<<grid, 32 * CAN_WARPS>>>(user, item, out, B);
}

// round 2
// speedup vs baseline: 1.0728x; 1.0728x over previous
#include <cuda_runtime.h>
#include <cuda_bf16.h>
#include <cstddef>

// CAN: per-sample 2-layer MLP, B=16384, N=50, D=16, fp32.
// x = relu(x @ W0 + b0); x = relu(x @ W1 + b1)
//
// Layout: block = 224 threads handles 8 samples (400 rows).
//   Lane t (t<200) owns rows 2t, 2t+1 of the block (always same sample, N even).
//   W (544 floats/sample) staged in shared, padded stride 552 to stagger banks.
//   x lives in registers end-to-end; W rows broadcast via LDS.128 (1 unique
//   address per in-sample lane group); accumulation in packed f32x2 FFMA2.

#define CAN_D 16
#define CAN_N 50
#define SAMPLES_PER_BLK 8
#define THREADS_PER_BLK 224
#define ACTIVE_LANES 200            // 8 samples * 50 rows / 2 rows per lane
#define W_FLOATS 544                // 2*(256+16)
#define W_STRIDE 552                // padded (+32B) to stagger banks at sample seams

typedef unsigned long long ull;

#define FMA2(acc, x2, w2) \
    asm("fma.rn.f32x2 %0, %1, %2, %3;" : "=l"(acc) : "l"(x2), "l"(w2), "l"(acc))
#define PACK2(dst, f) \
    asm("mov.b64 %0, {%1, %1};" : "=l"(dst) : "r"(__float_as_uint(f)))
#define UNPACK2(lo, hi, p) \
    asm("mov.b64 {%0, %1}, %2;" : "=r"(lo), "=r"(hi) : "l"(p))

// One layer for a 2-row register tile. w points at this layer's slice:
// W rows at double2 idx [4d .. 4d+3], bias at [64..67]. In/out may alias.
__device__ __forceinline__ void can_layer(const double2* __restrict__ w,
                                          float x0[CAN_D], float x1[CAN_D])
{
    ull a0[8], a1[8];
    #pragma unroll
    for (int q = 0; q < 4; ++q) {            // bias init (4 LDS.128)
        double2 b = w[64 + q];
        a0[2 * q]     = __double_as_longlong(b.x);
        a0[2 * q + 1] = __double_as_longlong(b.y);
        a1[2 * q]     = a0[2 * q];
        a1[2 * q + 1] = a0[2 * q + 1];
    }
    #pragma unroll
    for (int d = 0; d < CAN_D; ++d) {
        ull p0, p1;
        PACK2(p0, x0[d]);
        PACK2(p1, x1[d]);
        #pragma unroll
        for (int q = 0; q < 4; ++q) {        // W row d: 4 LDS.128, broadcast
            double2 wv = w[4 * d + q];
            ull wlo = __double_as_longlong(wv.x);
            ull whi = __double_as_longlong(wv.y);
            FMA2(a0[2 * q],     p0, wlo);
            FMA2(a0[2 * q + 1], p0, whi);
            FMA2(a1[2 * q],     p1, wlo);
            FMA2(a1[2 * q + 1], p1, whi);
        }
    }
    #pragma unroll
    for (int k = 0; k < 8; ++k) {            // unpack + ReLU (ALU pipe)
        unsigned lo, hi;
        UNPACK2(lo, hi, a0[k]);
        x0[2 * k]     = fmaxf(__uint_as_float(lo), 0.0f);
        x0[2 * k + 1] = fmaxf(__uint_as_float(hi), 0.0f);
        UNPACK2(lo, hi, a1[k]);
        x1[2 * k]     = fmaxf(__uint_as_float(lo), 0.0f);
        x1[2 * k + 1] = fmaxf(__uint_as_float(hi), 0.0f);
    }
}

__global__ __launch_bounds__(THREADS_PER_BLK, 3)
void can_kernel(const float* __restrict__ user,
                const float* __restrict__ item,
                float* __restrict__ out,
                int B)
{
    __shared__ __align__(16) float ws[SAMPLES_PER_BLK * W_STRIDE];

    const int tid   = threadIdx.x;
    const int sbase = blockIdx.x * SAMPLES_PER_BLK;

    // ---- stage W for up to 8 samples: coalesced float4 copy ----
    {
        const int nsamp   = min(SAMPLES_PER_BLK, B - sbase);
        const int nfloat4 = nsamp * (W_FLOATS / 4);      // 136 per sample
        const float4* __restrict__ src =
            reinterpret_cast<const float4*>(item + (size_t)sbase * W_FLOATS);
        for (int i = tid; i < nfloat4; i += THREADS_PER_BLK) {
            int s = i / (W_FLOATS / 4);
            int r = i % (W_FLOATS / 4);
            *reinterpret_cast<float4*>(ws + s * W_STRIDE + r * 4) = src[i];
        }
    }
    __syncthreads();

    if (tid >= ACTIVE_LANES) return;
    const int sl = tid / (CAN_N / 2);                    // local sample (t/25)
    if (sbase + sl >= B) return;

    const int g0 = blockIdx.x * (SAMPLES_PER_BLK * CAN_N) + 2 * tid;  // global row

    // ---- load 2 x rows into registers (8 coalesced LDG.128) ----
    float x0[CAN_D], x1[CAN_D];
    {
        const float4* __restrict__ xin =
            reinterpret_cast<const float4*>(user + (size_t)g0 * CAN_D);
        #pragma unroll
        for (int q = 0; q < 4; ++q) {
            float4 v = xin[q];
            x0[4 * q] = v.x; x0[4 * q + 1] = v.y; x0[4 * q + 2] = v.z; x0[4 * q + 3] = v.w;
        }
        #pragma unroll
        for (int q = 0; q < 4; ++q) {
            float4 v = xin[4 + q];
            x1[4 * q] = v.x; x1[4 * q + 1] = v.y; x1[4 * q + 2] = v.z; x1[4 * q + 3] = v.w;
        }
    }

    const double2* __restrict__ wbase =
        reinterpret_cast<const double2*>(ws + sl * W_STRIDE);

    can_layer(wbase,      x0, x1);   // layer 0: rows at [0..63], bias [64..67]
    can_layer(wbase + 68, x0, x1);   // layer 1: same relative layout at +272 floats

    // ---- store 2 rows (8 coalesced STG.128) ----
    {
        float4* __restrict__ o = reinterpret_cast<float4*>(out + (size_t)g0 * CAN_D);
        #pragma unroll
        for (int q = 0; q < 4; ++q)
            o[q] = make_float4(x0[4 * q], x0[4 * q + 1], x0[4 * q + 2], x0[4 * q + 3]);
        #pragma unroll
        for (int q = 0; q < 4; ++q)
            o[4 + q] = make_float4(x1[4 * q], x1[4 * q + 1], x1[4 * q + 2], x1[4 * q + 3]);
    }
}

extern "C" void kernel_launch(void* const* d_in, const int* in_sizes, int n_in,
                              void* d_out, int out_size)
{
    const float* user = (const float*)d_in[0];
    const float* item = (const float*)d_in[1];
    float* out = (float*)d_out;

    const int B = in_sizes[0] / (CAN_N * CAN_D);        // 16384
    const int grid = (B + SAMPLES_PER_BLK - 1) / SAMPLES_PER_BLK;

    can_kernel<<<grid, THREADS_PER_BLK>>>(user, item, out, B);
}